// round 1
// baseline (speedup 1.0000x reference)
#include <cuda_runtime.h>
#include <math.h>

#define LAGSN 2
#define DN    64
#define HIDN  64
#define BN    16
#define TTN   1026
#define LENN  1024
#define TILE  256
#define NTOT  (BN*LENN)     /* 16384 */

#define PADX  65            /* xs row pad: conflict-free per-thread strided reads */
#define PW    68            /* weight row pad: 16B-aligned broadcast LDS.128 */

// scratch: per-(sample, channel) log|dJ| — deterministic reduction afterwards
__device__ float g_logpart[NTOT * DN];

__global__ __launch_bounds__(256, 1)
void fused_mlp_kernel(const float* __restrict__ x,
                      const float* __restrict__ W1,
                      const float* __restrict__ b1,
                      const float* __restrict__ W2,
                      const float* __restrict__ b2,
                      const float* __restrict__ W3,
                      const float* __restrict__ b3,
                      float* __restrict__ out_res)
{
    const int tid = threadIdx.x;
    const int l   = blockIdx.x;          // channel
    const int tb  = blockIdx.y;          // sample tile
    const int bb  = tb >> 2;             // batch index
    const int t0  = (tb & 3) * TILE;     // tile start within sequence

    extern __shared__ float sm[];
    float* xs  = sm;                     // 258 rows x PADX  (window t0 .. t0+257)
    float* W1T = xs  + 258 * PADX;       // [f=0..128][h]  (f=128 is w1_last row)
    float* W2T = W1T + 129 * PW;         // [h][g]
    float* W2w = W2T + HIDN * PW;        // [h][g] = w1_last[h]*W2T[h][g]
    float* b1s = W2w + HIDN * PW;        // 64
    float* b2s = b1s + 64;               // 64
    float* w3s = b2s + 64;               // 64

    // ---- cooperative loads ----
    {
        const float* xg = x + (size_t)(bb * TTN + t0) * DN;
        for (int idx = tid; idx < 258 * DN; idx += 256) {
            int r = idx >> 6, d = idx & 63;
            xs[r * PADX + d] = xg[idx];
        }
        const float* W1g = W1 + (size_t)l * HIDN * 129;
        for (int idx = tid; idx < HIDN * 129; idx += 256) {
            int h = idx / 129;
            int f = idx - h * 129;
            W1T[f * PW + h] = W1g[idx];          // coalesced read, transposed write
        }
        const float* W2g = W2 + (size_t)l * HIDN * HIDN;
        for (int idx = tid; idx < HIDN * HIDN; idx += 256) {
            int g = idx >> 6, h = idx & 63;
            W2T[h * PW + g] = W2g[idx];
        }
        if (tid < 64) {
            b1s[tid] = b1[l * HIDN + tid];
            b2s[tid] = b2[l * HIDN + tid];
            w3s[tid] = W3[l * HIDN + tid];       // W3[l,0,:]
        }
    }
    __syncthreads();
    // W2w[h][g] = w1_last[h] * W2T[h][g]
    for (int idx = tid; idx < HIDN * HIDN; idx += 256) {
        int g = idx >> 6, h = idx & 63;
        W2w[h * PW + g] = W1T[128 * PW + h] * W2T[h * PW + g];
    }
    __syncthreads();

    // ---- phase A: z1 = W1 @ feat (+ x_t * w1_last) + b1, per-sample in registers ----
    float a1[HIDN];
    #pragma unroll
    for (int h = 0; h < HIDN; h++) a1[h] = b1s[h];

    const float* xrow = xs + tid * PADX;     // rows tid (lag0), tid+1 (lag1), tid+2 (x_t)

    #pragma unroll 4
    for (int d = 0; d < 64; d++) {           // lag 0 features
        float feat = xrow[d];
        const float* w = W1T + d * PW;
        #pragma unroll
        for (int h = 0; h < HIDN; h++) a1[h] = fmaf(feat, w[h], a1[h]);
    }
    #pragma unroll 4
    for (int d = 0; d < 64; d++) {           // lag 1 features
        float feat = xrow[PADX + d];
        const float* w = W1T + (64 + d) * PW;
        #pragma unroll
        for (int h = 0; h < HIDN; h++) a1[h] = fmaf(feat, w[h], a1[h]);
    }
    {                                        // f = 128: x_t[n, l] * w1_last
        float xt = xrow[2 * PADX + l];
        const float* w = W1T + 128 * PW;
        #pragma unroll
        for (int h = 0; h < HIDN; h++) a1[h] = fmaf(xt, w[h], a1[h]);
    }
    #pragma unroll
    for (int h = 0; h < HIDN; h++) {         // leaky in place; sign survives for dleaky
        float z = a1[h];
        a1[h] = (z > 0.f) ? z : 0.01f * z;
    }

    // ---- phase B: z2 / tangent GEMM + output heads ----
    float outv = __ldg(&b3[l]);
    float dJ   = 0.f;

    #pragma unroll 1
    for (int gc = 0; gc < 4; gc++) {         // 16 g-columns at a time
        float accA[16], accT[16];
        #pragma unroll
        for (int j = 0; j < 16; j++) { accA[j] = b2s[gc * 16 + j]; accT[j] = 0.f; }

        #pragma unroll
        for (int h = 0; h < HIDN; h++) {
            float a = a1[h];
            float c = (a > 0.f) ? 1.0f : 0.01f;   // dleaky(z1[h])
            const float* w2 = W2T + h * PW + gc * 16;
            const float* ww = W2w + h * PW + gc * 16;
            #pragma unroll
            for (int j = 0; j < 16; j++) {
                accA[j] = fmaf(a, w2[j], accA[j]);
                accT[j] = fmaf(c, ww[j], accT[j]);
            }
        }
        #pragma unroll
        for (int j = 0; j < 16; j++) {
            float z2  = accA[j];
            float a2  = (z2 > 0.f) ? z2 : 0.01f * z2;
            float t2  = ((z2 > 0.f) ? 1.0f : 0.01f) * accT[j];
            float w3v = w3s[gc * 16 + j];
            outv = fmaf(a2, w3v, outv);
            dJ   = fmaf(t2, w3v, dJ);
        }
    }

    const int n = bb * LENN + t0 + tid;
    out_res[(size_t)n * DN + l]   = outv;                 // residuals[b,t,l]
    g_logpart[(size_t)n * DN + l] = logf(fabsf(dJ));
}

// deterministic sum over channels: log_abs_det[b,t] = sum_l log|dJ[l,n]|
__global__ void reduce_log_kernel(float* __restrict__ out_log)
{
    int n = blockIdx.x * blockDim.x + threadIdx.x;   // 0 .. NTOT-1
    const float4* p = reinterpret_cast<const float4*>(g_logpart + (size_t)n * DN);
    float s = 0.f;
    #pragma unroll
    for (int i = 0; i < 16; i++) {
        float4 v = p[i];
        s += (v.x + v.y) + (v.z + v.w);
    }
    out_log[n] = s;
}

extern "C" void kernel_launch(void* const* d_in, const int* in_sizes, int n_in,
                              void* d_out, int out_size)
{
    const float* x  = (const float*)d_in[0];
    const float* W1 = (const float*)d_in[1];
    const float* b1 = (const float*)d_in[2];
    const float* W2 = (const float*)d_in[3];
    const float* b2 = (const float*)d_in[4];
    const float* W3 = (const float*)d_in[5];
    const float* b3 = (const float*)d_in[6];
    float* out = (float*)d_out;

    const size_t smem = (258 * PADX + 129 * PW + 2 * HIDN * PW + 192) * sizeof(float);
    cudaFuncSetAttribute(fused_mlp_kernel,
                         cudaFuncAttributeMaxDynamicSharedMemorySize, (int)smem);

    fused_mlp_kernel<<<dim3(64, 64), 256, smem>>>(x, W1, b1, W2, b2, W3, b3, out);
    reduce_log_kernel<<<NTOT / 256, 256>>>(out + (size_t)NTOT * DN);
}

// round 2
// speedup vs baseline: 1.0384x; 1.0384x over previous
#include <cuda_runtime.h>
#include <math.h>

#define LAGSN 2
#define DN    64
#define HIDN  64
#define BN    16
#define TTN   1026
#define LENN  1024
#define TILE  256
#define NTOT  (BN*LENN)     /* 16384 */

#define PADX  65            /* xs row pad: conflict-free per-thread strided reads */
#define PW    68            /* weight row pad: 16B-aligned rows (272B) for LDS.128 */

/* 16B-aligned shared-region offsets (floats) */
#define OFF_XS   0
#define OFF_W1T  16772              /* 258*65=16770 padded to mult of 4 */
#define OFF_W2T  (OFF_W1T + 129*PW)            /* 25544 */
#define OFF_W2W  (OFF_W2T + HIDN*PW)           /* 29896 */
#define OFF_B1   (OFF_W2W + HIDN*PW)           /* 34248 */
#define OFF_B2   (OFF_B1 + 64)
#define OFF_W3   (OFF_B2 + 64)
#define SMEM_F   (OFF_W3 + 64)

// scratch: per-(sample, channel) log|dJ| — deterministic reduction afterwards
__device__ float g_logpart[NTOT * DN];

typedef unsigned long long u64;

__device__ __forceinline__ u64 pack2(float v) {
    u64 r;
    asm("mov.b64 %0, {%1, %1};" : "=l"(r) : "f"(v));
    return r;
}
__device__ __forceinline__ void ffma2(u64& d, u64 a, u64 b) {
    asm("fma.rn.f32x2 %0, %1, %2, %0;" : "+l"(d) : "l"(a), "l"(b));
}
__device__ __forceinline__ float2 unpack2(u64 v) {
    float2 f;
    asm("mov.b64 {%0, %1}, %2;" : "=f"(f.x), "=f"(f.y) : "l"(v));
    return f;
}

__global__ __launch_bounds__(256, 1)
void fused_mlp_kernel(const float* __restrict__ x,
                      const float* __restrict__ W1,
                      const float* __restrict__ b1,
                      const float* __restrict__ W2,
                      const float* __restrict__ b2,
                      const float* __restrict__ W3,
                      const float* __restrict__ b3,
                      float* __restrict__ out_res)
{
    const int tid = threadIdx.x;
    const int l   = blockIdx.x;          // channel
    const int tb  = blockIdx.y;          // sample tile
    const int bb  = tb >> 2;             // batch index
    const int t0  = (tb & 3) * TILE;     // tile start within sequence

    extern __shared__ float sm[];
    float* xs  = sm + OFF_XS;            // 258 rows x PADX  (window t0 .. t0+257)
    float* W1T = sm + OFF_W1T;           // [f=0..128][h]  (f=128 is w1_last row)
    float* W2T = sm + OFF_W2T;           // [h][g]
    float* W2w = sm + OFF_W2W;           // [h][g] = w1_last[h]*W2T[h][g]
    float* b1s = sm + OFF_B1;
    float* b2s = sm + OFF_B2;
    float* w3s = sm + OFF_W3;

    // ---- cooperative loads ----
    {
        const float* xg = x + (size_t)(bb * TTN + t0) * DN;
        for (int idx = tid; idx < 258 * DN; idx += 256) {
            int r = idx >> 6, d = idx & 63;
            xs[r * PADX + d] = xg[idx];
        }
        const float* W1g = W1 + (size_t)l * HIDN * 129;
        for (int idx = tid; idx < HIDN * 129; idx += 256) {
            int h = idx / 129;
            int f = idx - h * 129;
            W1T[f * PW + h] = W1g[idx];          // coalesced read, transposed write
        }
        const float* W2g = W2 + (size_t)l * HIDN * HIDN;
        for (int idx = tid; idx < HIDN * HIDN; idx += 256) {
            int g = idx >> 6, h = idx & 63;
            W2T[h * PW + g] = W2g[idx];
        }
        if (tid < 64) {
            b1s[tid] = b1[l * HIDN + tid];
            b2s[tid] = b2[l * HIDN + tid];
            w3s[tid] = W3[l * HIDN + tid];       // W3[l,0,:]
        }
    }
    __syncthreads();
    // W2w[h][g] = w1_last[h] * W2T[h][g]
    for (int idx = tid; idx < HIDN * HIDN; idx += 256) {
        int g = idx >> 6, h = idx & 63;
        W2w[h * PW + g] = W1T[128 * PW + h] * W2T[h * PW + g];
    }
    __syncthreads();

    // ---- phase A: z1 = W1 @ feat (+ x_t * w1_last) + b1, packed h-pairs ----
    u64 a1p[32];
    #pragma unroll
    for (int j = 0; j < 32; j++)
        a1p[j] = reinterpret_cast<const u64*>(b1s)[j];

    const float* xrow = xs + tid * PADX;     // rows tid (lag0), tid+1 (lag1), tid+2 (x_t)

    #pragma unroll 2
    for (int d = 0; d < 64; d++) {           // lag 0 features
        u64 f2 = pack2(xrow[d]);
        const ulonglong2* w = reinterpret_cast<const ulonglong2*>(W1T + d * PW);
        #pragma unroll
        for (int j = 0; j < 16; j++) {
            ulonglong2 wv = w[j];            // LDS.128 broadcast
            ffma2(a1p[2*j],   f2, wv.x);
            ffma2(a1p[2*j+1], f2, wv.y);
        }
    }
    #pragma unroll 2
    for (int d = 0; d < 64; d++) {           // lag 1 features
        u64 f2 = pack2(xrow[PADX + d]);
        const ulonglong2* w = reinterpret_cast<const ulonglong2*>(W1T + (64 + d) * PW);
        #pragma unroll
        for (int j = 0; j < 16; j++) {
            ulonglong2 wv = w[j];
            ffma2(a1p[2*j],   f2, wv.x);
            ffma2(a1p[2*j+1], f2, wv.y);
        }
    }
    {                                        // f = 128: x_t[n, l] * w1_last
        u64 f2 = pack2(xrow[2 * PADX + l]);
        const ulonglong2* w = reinterpret_cast<const ulonglong2*>(W1T + 128 * PW);
        #pragma unroll
        for (int j = 0; j < 16; j++) {
            ulonglong2 wv = w[j];
            ffma2(a1p[2*j],   f2, wv.x);
            ffma2(a1p[2*j+1], f2, wv.y);
        }
    }

    // leaky activation; keep scalar a1 (sign recovers dleaky)
    float a1[HIDN];
    #pragma unroll
    for (int j = 0; j < 32; j++) {
        float2 v = unpack2(a1p[j]);
        a1[2*j]   = (v.x > 0.f) ? v.x : 0.01f * v.x;
        a1[2*j+1] = (v.y > 0.f) ? v.y : 0.01f * v.y;
    }

    // ---- phase B: z2 / tangent GEMM + output heads (packed g-pairs) ----
    float outv = __ldg(&b3[l]);
    float dJ   = 0.f;

    #pragma unroll 1
    for (int gc = 0; gc < 4; gc++) {         // 16 g-columns at a time
        u64 accA[8], accT[8];
        #pragma unroll
        for (int j = 0; j < 8; j++) {
            accA[j] = reinterpret_cast<const u64*>(b2s + gc * 16)[j];
            accT[j] = 0ull;                  // bits of (0.f, 0.f)
        }

        #pragma unroll 8
        for (int h = 0; h < HIDN; h++) {
            float a = a1[h];
            u64 ap = pack2(a);
            u64 cp = pack2((a > 0.f) ? 1.0f : 0.01f);   // dleaky(z1[h])
            const ulonglong2* w2 = reinterpret_cast<const ulonglong2*>(W2T + h * PW + gc * 16);
            const ulonglong2* ww = reinterpret_cast<const ulonglong2*>(W2w + h * PW + gc * 16);
            #pragma unroll
            for (int j = 0; j < 4; j++) {
                ulonglong2 wv = w2[j];
                ffma2(accA[2*j],   ap, wv.x);
                ffma2(accA[2*j+1], ap, wv.y);
                ulonglong2 tv = ww[j];
                ffma2(accT[2*j],   cp, tv.x);
                ffma2(accT[2*j+1], cp, tv.y);
            }
        }
        #pragma unroll
        for (int j = 0; j < 8; j++) {
            float2 zA = unpack2(accA[j]);
            float2 zT = unpack2(accT[j]);
            float w3a = w3s[gc * 16 + 2*j];
            float w3b = w3s[gc * 16 + 2*j + 1];
            float a2a = (zA.x > 0.f) ? zA.x : 0.01f * zA.x;
            float a2b = (zA.y > 0.f) ? zA.y : 0.01f * zA.y;
            float t2a = ((zA.x > 0.f) ? 1.0f : 0.01f) * zT.x;
            float t2b = ((zA.y > 0.f) ? 1.0f : 0.01f) * zT.y;
            outv = fmaf(a2a, w3a, outv);
            outv = fmaf(a2b, w3b, outv);
            dJ   = fmaf(t2a, w3a, dJ);
            dJ   = fmaf(t2b, w3b, dJ);
        }
    }

    const int n = bb * LENN + t0 + tid;
    out_res[(size_t)n * DN + l]   = outv;                 // residuals[b,t,l]
    g_logpart[(size_t)n * DN + l] = logf(fabsf(dJ));
}

// deterministic sum over channels: log_abs_det[b,t] = sum_l log|dJ[l,n]|
__global__ void reduce_log_kernel(float* __restrict__ out_log)
{
    int n = blockIdx.x * blockDim.x + threadIdx.x;   // 0 .. NTOT-1
    const float4* p = reinterpret_cast<const float4*>(g_logpart + (size_t)n * DN);
    float s = 0.f;
    #pragma unroll
    for (int i = 0; i < 16; i++) {
        float4 v = p[i];
        s += (v.x + v.y) + (v.z + v.w);
    }
    out_log[n] = s;
}

extern "C" void kernel_launch(void* const* d_in, const int* in_sizes, int n_in,
                              void* d_out, int out_size)
{
    const float* x  = (const float*)d_in[0];
    const float* W1 = (const float*)d_in[1];
    const float* b1 = (const float*)d_in[2];
    const float* W2 = (const float*)d_in[3];
    const float* b2 = (const float*)d_in[4];
    const float* W3 = (const float*)d_in[5];
    const float* b3 = (const float*)d_in[6];
    float* out = (float*)d_out;

    const size_t smem = SMEM_F * sizeof(float);
    cudaFuncSetAttribute(fused_mlp_kernel,
                         cudaFuncAttributeMaxDynamicSharedMemorySize, (int)smem);

    fused_mlp_kernel<<<dim3(64, 64), 256, smem>>>(x, W1, b1, W2, b2, W3, b3, out);
    reduce_log_kernel<<<NTOT / 256, 256>>>(out + (size_t)NTOT * DN);
}

// round 3
// speedup vs baseline: 1.1847x; 1.1409x over previous
#include <cuda_runtime.h>
#include <math.h>

#define LAGSN 2
#define DN    64
#define HIDN  64
#define BN    16
#define TTN   1026
#define LENN  1024
#define TILE  512           /* samples per CTA; 2 per thread (tid, tid+256) */
#define NTOT  (BN*LENN)     /* 16384 */

#define PADX  65            /* xs row pad: conflict-free per-thread strided reads */
#define PW    68            /* weight row pad: 16B-aligned rows for LDS.128 */

/* 16B-aligned shared-region offsets (floats) */
#define OFF_XS   0                              /* 514 x PADX = 33410 -> pad 33412 */
#define OFF_W1T  33412
#define OFF_W2T  (OFF_W1T + 129*PW)             /* 42184 */
#define OFF_W2W  (OFF_W2T + HIDN*PW)            /* 46536 */
#define OFF_B1   (OFF_W2W + HIDN*PW)            /* 50888 */
#define OFF_B2   (OFF_B1 + 64)
#define OFF_W3   (OFF_B2 + 64)
#define SMEM_F   (OFF_W3 + 64)                  /* 51080 floats = 204320 B */

// scratch: per-(sample, channel) log|dJ| — deterministic reduction afterwards
__device__ float g_logpart[NTOT * DN];

typedef unsigned long long u64;

__device__ __forceinline__ u64 pack2(float v) {
    u64 r;
    asm("mov.b64 %0, {%1, %1};" : "=l"(r) : "f"(v));
    return r;
}
__device__ __forceinline__ void ffma2(u64& d, u64 a, u64 b) {
    asm("fma.rn.f32x2 %0, %1, %2, %0;" : "+l"(d) : "l"(a), "l"(b));
}
__device__ __forceinline__ float2 unpack2(u64 v) {
    float2 f;
    asm("mov.b64 {%0, %1}, %2;" : "=f"(f.x), "=f"(f.y) : "l"(v));
    return f;
}

__global__ __launch_bounds__(256, 1)
void fused_mlp_kernel(const float* __restrict__ x,
                      const float* __restrict__ W1,
                      const float* __restrict__ b1,
                      const float* __restrict__ W2,
                      const float* __restrict__ b2,
                      const float* __restrict__ W3,
                      const float* __restrict__ b3,
                      float* __restrict__ out_res)
{
    const int tid = threadIdx.x;
    const int l   = blockIdx.x;          // channel
    const int tb  = blockIdx.y;          // sample tile (2 per batch)
    const int bb  = tb >> 1;             // batch index
    const int t0  = (tb & 1) * TILE;     // tile start within sequence

    extern __shared__ float sm[];
    float* xs  = sm + OFF_XS;            // 514 rows x PADX (window t0 .. t0+513)
    float* W1T = sm + OFF_W1T;           // [f=0..128][h]  (f=128 is w1_last row)
    float* W2T = sm + OFF_W2T;           // [h][g]
    float* W2w = sm + OFF_W2W;           // [h][g] = w1_last[h]*W2T[h][g]
    float* b1s = sm + OFF_B1;
    float* b2s = sm + OFF_B2;
    float* w3s = sm + OFF_W3;

    // ---- cooperative loads ----
    {
        const float* xg = x + (size_t)(bb * TTN + t0) * DN;
        for (int idx = tid; idx < 514 * DN; idx += 256) {
            int r = idx >> 6, d = idx & 63;
            xs[r * PADX + d] = xg[idx];
        }
        const float* W1g = W1 + (size_t)l * HIDN * 129;
        for (int idx = tid; idx < HIDN * 129; idx += 256) {
            int h = idx / 129;
            int f = idx - h * 129;
            W1T[f * PW + h] = W1g[idx];          // coalesced read, transposed write
        }
        const float* W2g = W2 + (size_t)l * HIDN * HIDN;
        for (int idx = tid; idx < HIDN * HIDN; idx += 256) {
            int g = idx >> 6, h = idx & 63;
            W2T[h * PW + g] = W2g[idx];
        }
        if (tid < 64) {
            b1s[tid] = b1[l * HIDN + tid];
            b2s[tid] = b2[l * HIDN + tid];
            w3s[tid] = W3[l * HIDN + tid];       // W3[l,0,:]
        }
    }
    __syncthreads();
    // W2w[h][g] = w1_last[h] * W2T[h][g]
    for (int idx = tid; idx < HIDN * HIDN; idx += 256) {
        int g = idx >> 6, h = idx & 63;
        W2w[h * PW + g] = W1T[128 * PW + h] * W2T[h * PW + g];
    }
    __syncthreads();

    // ---- phase A: z1 for BOTH samples, packed h-pairs; weights reused 2x ----
    u64 accA0[32], accA1[32];
    #pragma unroll
    for (int j = 0; j < 32; j++) {
        u64 bv = reinterpret_cast<const u64*>(b1s)[j];
        accA0[j] = bv; accA1[j] = bv;
    }

    const float* xra = xs + tid * PADX;           // sample A rows tid, tid+1, tid+2
    const float* xrb = xs + (tid + 256) * PADX;   // sample B rows +256

    #pragma unroll 2
    for (int d = 0; d < 64; d++) {           // lag 0 features
        u64 fa = pack2(xra[d]);
        u64 fb = pack2(xrb[d]);
        const ulonglong2* w = reinterpret_cast<const ulonglong2*>(W1T + d * PW);
        #pragma unroll
        for (int j = 0; j < 16; j++) {
            ulonglong2 wv = w[j];            // LDS.128 broadcast, feeds 4 FFMA2
            ffma2(accA0[2*j],   fa, wv.x);
            ffma2(accA0[2*j+1], fa, wv.y);
            ffma2(accA1[2*j],   fb, wv.x);
            ffma2(accA1[2*j+1], fb, wv.y);
        }
    }
    #pragma unroll 2
    for (int d = 0; d < 64; d++) {           // lag 1 features
        u64 fa = pack2(xra[PADX + d]);
        u64 fb = pack2(xrb[PADX + d]);
        const ulonglong2* w = reinterpret_cast<const ulonglong2*>(W1T + (64 + d) * PW);
        #pragma unroll
        for (int j = 0; j < 16; j++) {
            ulonglong2 wv = w[j];
            ffma2(accA0[2*j],   fa, wv.x);
            ffma2(accA0[2*j+1], fa, wv.y);
            ffma2(accA1[2*j],   fb, wv.x);
            ffma2(accA1[2*j+1], fb, wv.y);
        }
    }
    {                                        // f = 128: x_t[n, l] * w1_last
        u64 fa = pack2(xra[2 * PADX + l]);
        u64 fb = pack2(xrb[2 * PADX + l]);
        const ulonglong2* w = reinterpret_cast<const ulonglong2*>(W1T + 128 * PW);
        #pragma unroll
        for (int j = 0; j < 16; j++) {
            ulonglong2 wv = w[j];
            ffma2(accA0[2*j],   fa, wv.x);
            ffma2(accA0[2*j+1], fa, wv.y);
            ffma2(accA1[2*j],   fb, wv.x);
            ffma2(accA1[2*j+1], fb, wv.y);
        }
    }

    // leaky activation; keep scalar a1 per sample (sign recovers dleaky)
    float a1a[HIDN], a1b[HIDN];
    #pragma unroll
    for (int j = 0; j < 32; j++) {
        float2 va = unpack2(accA0[j]);
        a1a[2*j]   = (va.x > 0.f) ? va.x : 0.01f * va.x;
        a1a[2*j+1] = (va.y > 0.f) ? va.y : 0.01f * va.y;
        float2 vb = unpack2(accA1[j]);
        a1b[2*j]   = (vb.x > 0.f) ? vb.x : 0.01f * vb.x;
        a1b[2*j+1] = (vb.y > 0.f) ? vb.y : 0.01f * vb.y;
    }

    // ---- phase B: z2 / tangent GEMM for both samples; weights reused 2x ----
    float b3v  = __ldg(&b3[l]);
    float out0 = b3v, out1 = b3v;
    float dJ0  = 0.f, dJ1  = 0.f;

    #pragma unroll 1
    for (int gc = 0; gc < 8; gc++) {         // 8 g-columns at a time
        u64 zA0[4], zT0[4], zA1[4], zT1[4];
        #pragma unroll
        for (int j = 0; j < 4; j++) {
            u64 bv = reinterpret_cast<const u64*>(b2s + gc * 8)[j];
            zA0[j] = bv; zA1[j] = bv;
            zT0[j] = 0ull; zT1[j] = 0ull;
        }

        #pragma unroll 4
        for (int h = 0; h < HIDN; h++) {
            float a0 = a1a[h];
            float a1v = a1b[h];
            u64 ap0 = pack2(a0);
            u64 cp0 = pack2((a0 > 0.f) ? 1.0f : 0.01f);
            u64 ap1 = pack2(a1v);
            u64 cp1 = pack2((a1v > 0.f) ? 1.0f : 0.01f);
            const ulonglong2* w2 = reinterpret_cast<const ulonglong2*>(W2T + h * PW + gc * 8);
            const ulonglong2* ww = reinterpret_cast<const ulonglong2*>(W2w + h * PW + gc * 8);
            #pragma unroll
            for (int j = 0; j < 2; j++) {
                ulonglong2 wv = w2[j];       // feeds 4 FFMA2
                ffma2(zA0[2*j],   ap0, wv.x);
                ffma2(zA0[2*j+1], ap0, wv.y);
                ffma2(zA1[2*j],   ap1, wv.x);
                ffma2(zA1[2*j+1], ap1, wv.y);
                ulonglong2 tv = ww[j];       // feeds 4 FFMA2
                ffma2(zT0[2*j],   cp0, tv.x);
                ffma2(zT0[2*j+1], cp0, tv.y);
                ffma2(zT1[2*j],   cp1, tv.x);
                ffma2(zT1[2*j+1], cp1, tv.y);
            }
        }
        #pragma unroll
        for (int j = 0; j < 4; j++) {
            float w3a = w3s[gc * 8 + 2*j];
            float w3b = w3s[gc * 8 + 2*j + 1];
            {
                float2 zA = unpack2(zA0[j]);
                float2 zT = unpack2(zT0[j]);
                float a2a = (zA.x > 0.f) ? zA.x : 0.01f * zA.x;
                float a2b = (zA.y > 0.f) ? zA.y : 0.01f * zA.y;
                float t2a = ((zA.x > 0.f) ? 1.0f : 0.01f) * zT.x;
                float t2b = ((zA.y > 0.f) ? 1.0f : 0.01f) * zT.y;
                out0 = fmaf(a2a, w3a, out0);
                out0 = fmaf(a2b, w3b, out0);
                dJ0  = fmaf(t2a, w3a, dJ0);
                dJ0  = fmaf(t2b, w3b, dJ0);
            }
            {
                float2 zA = unpack2(zA1[j]);
                float2 zT = unpack2(zT1[j]);
                float a2a = (zA.x > 0.f) ? zA.x : 0.01f * zA.x;
                float a2b = (zA.y > 0.f) ? zA.y : 0.01f * zA.y;
                float t2a = ((zA.x > 0.f) ? 1.0f : 0.01f) * zT.x;
                float t2b = ((zA.y > 0.f) ? 1.0f : 0.01f) * zT.y;
                out1 = fmaf(a2a, w3a, out1);
                out1 = fmaf(a2b, w3b, out1);
                dJ1  = fmaf(t2a, w3a, dJ1);
                dJ1  = fmaf(t2b, w3b, dJ1);
            }
        }
    }

    const int na = bb * LENN + t0 + tid;
    const int nb = na + 256;
    out_res[(size_t)na * DN + l]   = out0;
    out_res[(size_t)nb * DN + l]   = out1;
    g_logpart[(size_t)na * DN + l] = logf(fabsf(dJ0));
    g_logpart[(size_t)nb * DN + l] = logf(fabsf(dJ1));
}

// deterministic sum over channels: log_abs_det[b,t] = sum_l log|dJ[l,n]|
__global__ void reduce_log_kernel(float* __restrict__ out_log)
{
    int n = blockIdx.x * blockDim.x + threadIdx.x;   // 0 .. NTOT-1
    const float4* p = reinterpret_cast<const float4*>(g_logpart + (size_t)n * DN);
    float s = 0.f;
    #pragma unroll
    for (int i = 0; i < 16; i++) {
        float4 v = p[i];
        s += (v.x + v.y) + (v.z + v.w);
    }
    out_log[n] = s;
}

extern "C" void kernel_launch(void* const* d_in, const int* in_sizes, int n_in,
                              void* d_out, int out_size)
{
    const float* x  = (const float*)d_in[0];
    const float* W1 = (const float*)d_in[1];
    const float* b1 = (const float*)d_in[2];
    const float* W2 = (const float*)d_in[3];
    const float* b2 = (const float*)d_in[4];
    const float* W3 = (const float*)d_in[5];
    const float* b3 = (const float*)d_in[6];
    float* out = (float*)d_out;

    const size_t smem = SMEM_F * sizeof(float);
    cudaFuncSetAttribute(fused_mlp_kernel,
                         cudaFuncAttributeMaxDynamicSharedMemorySize, (int)smem);

    fused_mlp_kernel<<<dim3(64, 32), 256, smem>>>(x, W1, b1, W2, b2, W3, b3, out);
    reduce_log_kernel<<<NTOT / 256, 256>>>(out + (size_t)NTOT * DN);
}

// round 5
// speedup vs baseline: 3.6770x; 3.1037x over previous
#include <cuda_runtime.h>
#include <cuda_bf16.h>
#include <math.h>
#include <stdint.h>

#define BN    16
#define TTN   1026
#define LENN  1024
#define NTOT  (BN*LENN)

/* ---- per-channel weight fragment blob (bytes) ---- */
#define WIMG_W1H   0
#define WIMG_W1L   16384
#define WIMG_W2H   32768
#define WIMG_W2L   40960
#define WIMG_WWH   49152
#define WIMG_WWL   57344
#define WIMG_SCAL  65536        /* b1[64] w1last[64] b2[64] w3[64] b3 -> 257 f32 */
#define WIMG_CPY   66576        /* bytes cp.async'd per channel (mult of 16) */
#define WIMG_STRIDE 66816

/* ---- smem layout (bytes) ---- */
#define SM_A1H  0
#define SM_A1L  32768
#define SM_WB0  65536
#define SM_WB1  (SM_WB0 + WIMG_CPY)
#define SM_XT   (SM_WB1 + WIMG_CPY)       /* 128 rows x 8 ch x f32 */
#define SM_TOTAL (SM_XT + 4096)

__device__ __align__(16) unsigned char g_wimg[64 * (size_t)WIMG_STRIDE];
__device__ __align__(16) uint4 g_a1h[128 * 2048];   /* A frags (hi) per tile: 32KB */
__device__ __align__(16) uint4 g_a1l[128 * 2048];   /* A frags (lo) */
__device__ float g_logpart[NTOT * 64];

/* ================= helpers ================= */
__device__ __forceinline__ uint32_t pkbf(float lo, float hi) {
    uint32_t r;
    asm("cvt.rn.bf16x2.f32 %0, %1, %2;" : "=r"(r) : "f"(hi), "f"(lo));
    return r;
}
__device__ __forceinline__ float bfh(float v) {       /* round-trip through bf16 */
    return __bfloat162float(__float2bfloat16_rn(v));
}
__device__ __forceinline__ void mma_bf16(float& d0, float& d1, float& d2, float& d3,
                                         uint32_t a0, uint32_t a1, uint32_t a2, uint32_t a3,
                                         uint32_t b0, uint32_t b1) {
    asm volatile("mma.sync.aligned.m16n8k16.row.col.f32.bf16.bf16.f32 "
        "{%0,%1,%2,%3}, {%4,%5,%6,%7}, {%8,%9}, {%0,%1,%2,%3};"
        : "+f"(d0), "+f"(d1), "+f"(d2), "+f"(d3)
        : "r"(a0), "r"(a1), "r"(a2), "r"(a3), "r"(b0), "r"(b1));
}
__device__ __forceinline__ void cpa16(uint32_t dst, const void* src) {
    asm volatile("cp.async.cg.shared.global [%0], [%1], 16;" :: "r"(dst), "l"(src) : "memory");
}
#define CPA_COMMIT() asm volatile("cp.async.commit_group;" ::: "memory")
#define CPA_WAIT(n)  asm volatile("cp.async.wait_group %0;" :: "n"(n) : "memory")

/* ================= prep: X -> split A fragments ================= */
__global__ void prep_x_kernel(const float* __restrict__ x)
{
    const int tile = blockIdx.x;
    const int bb = tile >> 3, t0 = (tile & 7) * 128;
    const int gid = blockIdx.y * 256 + threadIdx.x;      /* 0..2047 */
    const int ft = gid >> 5, lane = gid & 31;
    const int mt = ft >> 3, kt = ft & 7;
    const int row0 = mt * 16 + (lane >> 2);
    const int c0 = kt * 16 + (lane & 3) * 2;

    const float* xb = x + (size_t)(bb * TTN + t0 + row0) * 64;
    float2 p00 = *(const float2*)(xb + c0);
    float2 p10 = *(const float2*)(xb + 8 * 64 + c0);
    float2 p01 = *(const float2*)(xb + c0 + 8);
    float2 p11 = *(const float2*)(xb + 8 * 64 + c0 + 8);

    uint4 hi, lo;
    hi.x = pkbf(p00.x, p00.y); lo.x = pkbf(p00.x - bfh(p00.x), p00.y - bfh(p00.y));
    hi.y = pkbf(p10.x, p10.y); lo.y = pkbf(p10.x - bfh(p10.x), p10.y - bfh(p10.y));
    hi.z = pkbf(p01.x, p01.y); lo.z = pkbf(p01.x - bfh(p01.x), p01.y - bfh(p01.y));
    hi.w = pkbf(p11.x, p11.y); lo.w = pkbf(p11.x - bfh(p11.x), p11.y - bfh(p11.y));
    g_a1h[(size_t)tile * 2048 + gid] = hi;
    g_a1l[(size_t)tile * 2048 + gid] = lo;
}

/* ================= prep: weights -> B fragment blobs ================= */
__global__ void prep_w_kernel(const float* __restrict__ W1, const float* __restrict__ b1,
                              const float* __restrict__ W2, const float* __restrict__ b2,
                              const float* __restrict__ W3, const float* __restrict__ b3)
{
    const int l = blockIdx.x, tid = threadIdx.x;
    unsigned char* blob = g_wimg + (size_t)l * WIMG_STRIDE;
    const float* W1c = W1 + (size_t)l * 64 * 129;
    const float* W2c = W2 + (size_t)l * 64 * 64;

    /* W1 B-frags: kt 0..7, nt 0..7 */
    for (int idx = tid; idx < 2048; idx += 256) {
        int ft = idx >> 5, lane = idx & 31;
        int kt = ft >> 3, nt = ft & 7;
        int n0 = nt * 8 + (lane >> 2);
        int k0 = kt * 16 + (lane & 3) * 2;
        const float* wr = W1c + n0 * 129;
        float v0 = wr[k0], v1 = wr[k0 + 1], v2 = wr[k0 + 8], v3 = wr[k0 + 9];
        uint2 hi = make_uint2(pkbf(v0, v1), pkbf(v2, v3));
        uint2 lo = make_uint2(pkbf(v0 - bfh(v0), v1 - bfh(v1)),
                              pkbf(v2 - bfh(v2), v3 - bfh(v3)));
        *(uint2*)(blob + WIMG_W1H + idx * 8) = hi;
        *(uint2*)(blob + WIMG_W1L + idx * 8) = lo;
    }
    /* W2 and W2w B-frags: kt 0..3, nt 0..7 */
    for (int idx = tid; idx < 1024; idx += 256) {
        int ft = idx >> 5, lane = idx & 31;
        int kt = ft >> 3, nt = ft & 7;
        int n0 = nt * 8 + (lane >> 2);
        int k0 = kt * 16 + (lane & 3) * 2;
        float v0 = W2c[n0 * 64 + k0],     v1 = W2c[n0 * 64 + k0 + 1];
        float v2 = W2c[n0 * 64 + k0 + 8], v3 = W2c[n0 * 64 + k0 + 9];
        *(uint2*)(blob + WIMG_W2H + idx * 8) = make_uint2(pkbf(v0, v1), pkbf(v2, v3));
        *(uint2*)(blob + WIMG_W2L + idx * 8) = make_uint2(
            pkbf(v0 - bfh(v0), v1 - bfh(v1)), pkbf(v2 - bfh(v2), v3 - bfh(v3)));
        float u0 = 0.01f * W1c[(k0)     * 129 + 128] * v0;
        float u1 = 0.01f * W1c[(k0 + 1) * 129 + 128] * v1;
        float u2 = 0.01f * W1c[(k0 + 8) * 129 + 128] * v2;
        float u3 = 0.01f * W1c[(k0 + 9) * 129 + 128] * v3;
        *(uint2*)(blob + WIMG_WWH + idx * 8) = make_uint2(pkbf(u0, u1), pkbf(u2, u3));
        *(uint2*)(blob + WIMG_WWL + idx * 8) = make_uint2(
            pkbf(u0 - bfh(u0), u1 - bfh(u1)), pkbf(u2 - bfh(u2), u3 - bfh(u3)));
    }
    float* sc = (float*)(blob + WIMG_SCAL);
    if (tid < 64) {
        sc[tid]       = b1[l * 64 + tid];
        sc[64 + tid]  = W1c[tid * 129 + 128];   /* w1_last */
        sc[128 + tid] = b2[l * 64 + tid];
        sc[192 + tid] = W3[l * 64 + tid];
    }
    if (tid == 0) sc[256] = b3[l];
}

/* ================= main HMMA kernel ================= */
__global__ __launch_bounds__(128, 1)
void mlp_hmma_kernel(const float* __restrict__ x, float* __restrict__ out_res)
{
    extern __shared__ unsigned char smem[];
    const int tid = threadIdx.x;
    const int w = tid >> 5, lane = tid & 31;
    const int g = lane >> 2, tg = lane & 3;
    const int tile = blockIdx.x, bb = tile >> 3, t0 = (tile & 7) * 128;
    const int l0 = blockIdx.y * 8;
    const uint32_t sbase = (uint32_t)__cvta_generic_to_shared(smem);

    /* x_t staging: rows 0..127 x 8 channels (f32) */
    {
        const float4* src = (const float4*)(x + (size_t)(bb * TTN + t0 + tid + 2) * 64 + l0);
        float4 v0 = src[0], v1 = src[1];
        float4* d = (float4*)(smem + SM_XT + tid * 32);
        d[0] = v0; d[1] = v1;
    }

    /* group 0: A fragments + channel-0 weights */
    {
        const uint4* ah = g_a1h + (size_t)tile * 2048;
        const uint4* al = g_a1l + (size_t)tile * 2048;
        for (int i = tid; i < 2048; i += 128) {
            cpa16(sbase + SM_A1H + i * 16, ah + i);
            cpa16(sbase + SM_A1L + i * 16, al + i);
        }
        const uint4* wsrc = (const uint4*)(g_wimg + (size_t)l0 * WIMG_STRIDE);
        for (int i = tid; i < WIMG_CPY / 16; i += 128)
            cpa16(sbase + SM_WB0 + i * 16, wsrc + i);
        CPA_COMMIT();
    }

    const uint4* a1hq = (const uint4*)(smem + SM_A1H);
    const uint4* a1lq = (const uint4*)(smem + SM_A1L);

    for (int cj = 0; cj < 8; cj++) {
        const int l = l0 + cj;
        const unsigned char* wbp = smem + ((cj & 1) ? SM_WB1 : SM_WB0);

        __syncthreads();                       /* done reading prev buffer */
        if (cj < 7) {
            uint32_t nb = sbase + ((cj & 1) ? SM_WB0 : SM_WB1);
            const uint4* wsrc = (const uint4*)(g_wimg + (size_t)(l + 1) * WIMG_STRIDE);
            for (int i = tid; i < WIMG_CPY / 16; i += 128)
                cpa16(nb + i * 16, wsrc + i);
            CPA_COMMIT();
            CPA_WAIT(1);
        } else {
            CPA_WAIT(0);
        }
        __syncthreads();

        const float* sc = (const float*)(wbp + WIMG_SCAL);

        /* ---- GEMM1: z1 = X * W1^T (3 split passes) ---- */
        float z1[2][8][4];
        #pragma unroll
        for (int mt = 0; mt < 2; mt++)
            #pragma unroll
            for (int nt = 0; nt < 8; nt++)
                #pragma unroll
                for (int e = 0; e < 4; e++) z1[mt][nt][e] = 0.f;

        #pragma unroll 1
        for (int pass = 0; pass < 3; pass++) {
            const uint4* Aq = (pass < 2) ? a1hq : a1lq;
            const uint2* Bq = (const uint2*)(wbp + ((pass == 1) ? WIMG_W1L : WIMG_W1H));
            #pragma unroll 1
            for (int kt = 0; kt < 8; kt++) {
                uint4 af0 = Aq[((w * 2 + 0) * 8 + kt) * 32 + lane];
                uint4 af1 = Aq[((w * 2 + 1) * 8 + kt) * 32 + lane];
                #pragma unroll
                for (int nt = 0; nt < 8; nt++) {
                    uint2 bf = Bq[(kt * 8 + nt) * 32 + lane];
                    mma_bf16(z1[0][nt][0], z1[0][nt][1], z1[0][nt][2], z1[0][nt][3],
                             af0.x, af0.y, af0.z, af0.w, bf.x, bf.y);
                    mma_bf16(z1[1][nt][0], z1[1][nt][1], z1[1][nt][2], z1[1][nt][3],
                             af1.x, af1.y, af1.z, af1.w, bf.x, bf.y);
                }
            }
        }

        /* ---- epilogue 1: bias + rank-1, leaky, split -> register fragments ---- */
        uint32_t ah[2][4][4], al[2][4][4], cf[2][4][4];
        {
            const float* b1s  = sc;
            const float* w1ls = sc + 64;
            float xtr[2][2];
            #pragma unroll
            for (int mt = 0; mt < 2; mt++) {
                int r0 = (w * 2 + mt) * 16 + g;
                xtr[mt][0] = *(const float*)(smem + SM_XT + r0 * 32 + cj * 4);
                xtr[mt][1] = *(const float*)(smem + SM_XT + (r0 + 8) * 32 + cj * 4);
            }
            #pragma unroll
            for (int mt = 0; mt < 2; mt++)
            #pragma unroll
            for (int kt2 = 0; kt2 < 4; kt2++)
            #pragma unroll
            for (int half = 0; half < 2; half++) {
                int nt = kt2 * 2 + half;
                int col0 = nt * 8 + tg * 2;
                float b1a = b1s[col0], b1b = b1s[col0 + 1];
                float wla = w1ls[col0], wlb = w1ls[col0 + 1];
                float za = z1[mt][nt][0] + b1a + xtr[mt][0] * wla;
                float zb = z1[mt][nt][1] + b1b + xtr[mt][0] * wlb;
                float zc = z1[mt][nt][2] + b1a + xtr[mt][1] * wla;
                float zd = z1[mt][nt][3] + b1b + xtr[mt][1] * wlb;
                float aa = (za > 0.f) ? za : 0.01f * za;
                float ab = (zb > 0.f) ? zb : 0.01f * zb;
                float ac = (zc > 0.f) ? zc : 0.01f * zc;
                float ad = (zd > 0.f) ? zd : 0.01f * zd;
                ah[mt][kt2][half * 2 + 0] = pkbf(aa, ab);
                ah[mt][kt2][half * 2 + 1] = pkbf(ac, ad);
                al[mt][kt2][half * 2 + 0] = pkbf(aa - bfh(aa), ab - bfh(ab));
                al[mt][kt2][half * 2 + 1] = pkbf(ac - bfh(ac), ad - bfh(ad));
                uint32_t ca = (za > 0.f) ? 0x42C8u : 0x3F80u;   /* bf16(100), bf16(1) */
                uint32_t cb = (zb > 0.f) ? 0x42C8u : 0x3F80u;
                uint32_t cc = (zc > 0.f) ? 0x42C8u : 0x3F80u;
                uint32_t cd = (zd > 0.f) ? 0x42C8u : 0x3F80u;
                cf[mt][kt2][half * 2 + 0] = (cb << 16) | ca;
                cf[mt][kt2][half * 2 + 1] = (cd << 16) | cc;
            }
        }

        /* ---- GEMM-t: t2pre = c' * (0.01*w1last*W2)^T (2 passes) ---- */
        float tA[2][8][4];
        #pragma unroll
        for (int mt = 0; mt < 2; mt++)
            #pragma unroll
            for (int nt = 0; nt < 8; nt++)
                #pragma unroll
                for (int e = 0; e < 4; e++) tA[mt][nt][e] = 0.f;
        #pragma unroll 1
        for (int pass = 0; pass < 2; pass++) {
            const uint2* Bq = (const uint2*)(wbp + (pass ? WIMG_WWL : WIMG_WWH));
            #pragma unroll
            for (int kt = 0; kt < 4; kt++)
                #pragma unroll
                for (int nt = 0; nt < 8; nt++) {
                    uint2 bf = Bq[(kt * 8 + nt) * 32 + lane];
                    mma_bf16(tA[0][nt][0], tA[0][nt][1], tA[0][nt][2], tA[0][nt][3],
                             cf[0][kt][0], cf[0][kt][1], cf[0][kt][2], cf[0][kt][3], bf.x, bf.y);
                    mma_bf16(tA[1][nt][0], tA[1][nt][1], tA[1][nt][2], tA[1][nt][3],
                             cf[1][kt][0], cf[1][kt][1], cf[1][kt][2], cf[1][kt][3], bf.x, bf.y);
                }
        }

        /* ---- GEMM2: z2 = a1 * W2^T (3 passes) ---- */
        float zA[2][8][4];
        #pragma unroll
        for (int mt = 0; mt < 2; mt++)
            #pragma unroll
            for (int nt = 0; nt < 8; nt++)
                #pragma unroll
                for (int e = 0; e < 4; e++) zA[mt][nt][e] = 0.f;
        #pragma unroll 1
        for (int pass = 0; pass < 3; pass++) {
            const uint32_t (*Af)[4][4] = (pass < 2) ? ah : al;
            const uint2* Bq = (const uint2*)(wbp + ((pass == 1) ? WIMG_W2L : WIMG_W2H));
            #pragma unroll
            for (int kt = 0; kt < 4; kt++)
                #pragma unroll
                for (int nt = 0; nt < 8; nt++) {
                    uint2 bf = Bq[(kt * 8 + nt) * 32 + lane];
                    mma_bf16(zA[0][nt][0], zA[0][nt][1], zA[0][nt][2], zA[0][nt][3],
                             Af[0][kt][0], Af[0][kt][1], Af[0][kt][2], Af[0][kt][3], bf.x, bf.y);
                    mma_bf16(zA[1][nt][0], zA[1][nt][1], zA[1][nt][2], zA[1][nt][3],
                             Af[1][kt][0], Af[1][kt][1], Af[1][kt][2], Af[1][kt][3], bf.x, bf.y);
                }
        }

        /* ---- epilogue 2: leaky(z2), t2, output heads, quad reduce ---- */
        {
            const float* b2s = sc + 128;
            const float* w3s = sc + 192;
            const float b3v = sc[256];
            float po[2][2] = {{0.f, 0.f}, {0.f, 0.f}};
            float pd[2][2] = {{0.f, 0.f}, {0.f, 0.f}};
            #pragma unroll
            for (int mt = 0; mt < 2; mt++)
            #pragma unroll
            for (int nt = 0; nt < 8; nt++) {
                int col0 = nt * 8 + tg * 2;
                #pragma unroll
                for (int e = 0; e < 4; e++) {
                    int col = col0 + (e & 1);
                    int ri = e >> 1;
                    float z2 = zA[mt][nt][e] + b2s[col];
                    float a2 = (z2 > 0.f) ? z2 : 0.01f * z2;
                    float t2 = ((z2 > 0.f) ? 1.0f : 0.01f) * tA[mt][nt][e];
                    float w3v = w3s[col];
                    po[mt][ri] = fmaf(a2, w3v, po[mt][ri]);
                    pd[mt][ri] = fmaf(t2, w3v, pd[mt][ri]);
                }
            }
            #pragma unroll
            for (int mt = 0; mt < 2; mt++)
            #pragma unroll
            for (int ri = 0; ri < 2; ri++) {
                float o = po[mt][ri], dd = pd[mt][ri];
                o += __shfl_xor_sync(0xffffffffu, o, 1);
                o += __shfl_xor_sync(0xffffffffu, o, 2);
                dd += __shfl_xor_sync(0xffffffffu, dd, 1);
                dd += __shfl_xor_sync(0xffffffffu, dd, 2);
                if (tg == 0) {
                    int row = (w * 2 + mt) * 16 + g + ri * 8;
                    size_t n = (size_t)bb * LENN + t0 + row;
                    out_res[n * 64 + l]   = o + b3v;
                    g_logpart[n * 64 + l] = logf(fabsf(dd));
                }
            }
        }
    }
}

/* deterministic per-sample sum over 64 channels */
__global__ void reduce_log_kernel(float* __restrict__ out_log)
{
    int n = blockIdx.x * blockDim.x + threadIdx.x;
    const float4* p = reinterpret_cast<const float4*>(g_logpart + (size_t)n * 64);
    float s = 0.f;
    #pragma unroll
    for (int i = 0; i < 16; i++) {
        float4 v = p[i];
        s += (v.x + v.y) + (v.z + v.w);
    }
    out_log[n] = s;
}

extern "C" void kernel_launch(void* const* d_in, const int* in_sizes, int n_in,
                              void* d_out, int out_size)
{
    const float* x  = (const float*)d_in[0];
    const float* W1 = (const float*)d_in[1];
    const float* b1 = (const float*)d_in[2];
    const float* W2 = (const float*)d_in[3];
    const float* b2 = (const float*)d_in[4];
    const float* W3 = (const float*)d_in[5];
    const float* b3 = (const float*)d_in[6];
    float* out = (float*)d_out;

    prep_x_kernel<<<dim3(128, 8), 256>>>(x);
    prep_w_kernel<<<64, 256>>>(W1, b1, W2, b2, W3, b3);

    cudaFuncSetAttribute(mlp_hmma_kernel,
                         cudaFuncAttributeMaxDynamicSharedMemorySize, SM_TOTAL);
    mlp_hmma_kernel<<<dim3(128, 8), 128, SM_TOTAL>>>(x, out);
    reduce_log_kernel<<<NTOT / 256, 256>>>(out + (size_t)NTOT * 64);
}

// round 6
// speedup vs baseline: 3.9882x; 1.0846x over previous
#include <cuda_runtime.h>
#include <cuda_bf16.h>
#include <math.h>
#include <stdint.h>

#define BN    16
#define TTN   1026
#define LENN  1024
#define NTOT  (BN*LENN)

/* ---- per-channel weight fragment blob (bytes) ---- */
#define WIMG_W1H   0
#define WIMG_W1L   16384
#define WIMG_W2H   32768
#define WIMG_W2L   40960
#define WIMG_WWH   49152
#define WIMG_WWL   57344
#define WIMG_SCAL  65536        /* b1[64] w1last[64] b2[64] w3[64] b3 -> 257 f32 */
#define WIMG_STRIDE 66816

/* ---- smem layout (bytes): A fragments + x_t only ---- */
#define SM_A1H  0
#define SM_A1L  32768
#define SM_XT   65536            /* 128 rows x 8 ch x f32 */
#define SM_TOTAL (SM_XT + 4096)

__device__ __align__(16) unsigned char g_wimg[64 * (size_t)WIMG_STRIDE];
__device__ __align__(16) uint4 g_a1h[128 * 2048];
__device__ __align__(16) uint4 g_a1l[128 * 2048];
__device__ float g_logpart[NTOT * 64];

/* ================= helpers ================= */
__device__ __forceinline__ uint32_t pkbf(float lo, float hi) {
    uint32_t r;
    asm("cvt.rn.bf16x2.f32 %0, %1, %2;" : "=r"(r) : "f"(hi), "f"(lo));
    return r;
}
__device__ __forceinline__ float bfh(float v) {
    return __bfloat162float(__float2bfloat16_rn(v));
}
__device__ __forceinline__ void mma_bf16(float& d0, float& d1, float& d2, float& d3,
                                         uint32_t a0, uint32_t a1, uint32_t a2, uint32_t a3,
                                         uint32_t b0, uint32_t b1) {
    asm volatile("mma.sync.aligned.m16n8k16.row.col.f32.bf16.bf16.f32 "
        "{%0,%1,%2,%3}, {%4,%5,%6,%7}, {%8,%9}, {%0,%1,%2,%3};"
        : "+f"(d0), "+f"(d1), "+f"(d2), "+f"(d3)
        : "r"(a0), "r"(a1), "r"(a2), "r"(a3), "r"(b0), "r"(b1));
}
__device__ __forceinline__ void cpa16(uint32_t dst, const void* src) {
    asm volatile("cp.async.cg.shared.global [%0], [%1], 16;" :: "r"(dst), "l"(src) : "memory");
}
#define CPA_COMMIT() asm volatile("cp.async.commit_group;" ::: "memory")
#define CPA_WAIT(n)  asm volatile("cp.async.wait_group %0;" :: "n"(n) : "memory")

/* ================= prep: X -> split A fragments ================= */
__global__ void prep_x_kernel(const float* __restrict__ x)
{
    const int tile = blockIdx.x;
    const int bb = tile >> 3, t0 = (tile & 7) * 128;
    const int gid = blockIdx.y * 256 + threadIdx.x;
    const int ft = gid >> 5, lane = gid & 31;
    const int mt = ft >> 3, kt = ft & 7;
    const int row0 = mt * 16 + (lane >> 2);
    const int c0 = kt * 16 + (lane & 3) * 2;

    const float* xb = x + (size_t)(bb * TTN + t0 + row0) * 64;
    float2 p00 = *(const float2*)(xb + c0);
    float2 p10 = *(const float2*)(xb + 8 * 64 + c0);
    float2 p01 = *(const float2*)(xb + c0 + 8);
    float2 p11 = *(const float2*)(xb + 8 * 64 + c0 + 8);

    uint4 hi, lo;
    hi.x = pkbf(p00.x, p00.y); lo.x = pkbf(p00.x - bfh(p00.x), p00.y - bfh(p00.y));
    hi.y = pkbf(p10.x, p10.y); lo.y = pkbf(p10.x - bfh(p10.x), p10.y - bfh(p10.y));
    hi.z = pkbf(p01.x, p01.y); lo.z = pkbf(p01.x - bfh(p01.x), p01.y - bfh(p01.y));
    hi.w = pkbf(p11.x, p11.y); lo.w = pkbf(p11.x - bfh(p11.x), p11.y - bfh(p11.y));
    g_a1h[(size_t)tile * 2048 + gid] = hi;
    g_a1l[(size_t)tile * 2048 + gid] = lo;
}

/* ================= prep: weights -> B fragment blobs ================= */
__global__ void prep_w_kernel(const float* __restrict__ W1, const float* __restrict__ b1,
                              const float* __restrict__ W2, const float* __restrict__ b2,
                              const float* __restrict__ W3, const float* __restrict__ b3)
{
    const int l = blockIdx.x, tid = threadIdx.x;
    unsigned char* blob = g_wimg + (size_t)l * WIMG_STRIDE;
    const float* W1c = W1 + (size_t)l * 64 * 129;
    const float* W2c = W2 + (size_t)l * 64 * 64;

    for (int idx = tid; idx < 2048; idx += 256) {
        int ft = idx >> 5, lane = idx & 31;
        int kt = ft >> 3, nt = ft & 7;
        int n0 = nt * 8 + (lane >> 2);
        int k0 = kt * 16 + (lane & 3) * 2;
        const float* wr = W1c + n0 * 129;
        float v0 = wr[k0], v1 = wr[k0 + 1], v2 = wr[k0 + 8], v3 = wr[k0 + 9];
        *(uint2*)(blob + WIMG_W1H + idx * 8) = make_uint2(pkbf(v0, v1), pkbf(v2, v3));
        *(uint2*)(blob + WIMG_W1L + idx * 8) = make_uint2(
            pkbf(v0 - bfh(v0), v1 - bfh(v1)), pkbf(v2 - bfh(v2), v3 - bfh(v3)));
    }
    for (int idx = tid; idx < 1024; idx += 256) {
        int ft = idx >> 5, lane = idx & 31;
        int kt = ft >> 3, nt = ft & 7;
        int n0 = nt * 8 + (lane >> 2);
        int k0 = kt * 16 + (lane & 3) * 2;
        float v0 = W2c[n0 * 64 + k0],     v1 = W2c[n0 * 64 + k0 + 1];
        float v2 = W2c[n0 * 64 + k0 + 8], v3 = W2c[n0 * 64 + k0 + 9];
        *(uint2*)(blob + WIMG_W2H + idx * 8) = make_uint2(pkbf(v0, v1), pkbf(v2, v3));
        *(uint2*)(blob + WIMG_W2L + idx * 8) = make_uint2(
            pkbf(v0 - bfh(v0), v1 - bfh(v1)), pkbf(v2 - bfh(v2), v3 - bfh(v3)));
        float u0 = 0.01f * W1c[(k0)     * 129 + 128] * v0;
        float u1 = 0.01f * W1c[(k0 + 1) * 129 + 128] * v1;
        float u2 = 0.01f * W1c[(k0 + 8) * 129 + 128] * v2;
        float u3 = 0.01f * W1c[(k0 + 9) * 129 + 128] * v3;
        *(uint2*)(blob + WIMG_WWH + idx * 8) = make_uint2(pkbf(u0, u1), pkbf(u2, u3));
        *(uint2*)(blob + WIMG_WWL + idx * 8) = make_uint2(
            pkbf(u0 - bfh(u0), u1 - bfh(u1)), pkbf(u2 - bfh(u2), u3 - bfh(u3)));
    }
    float* sc = (float*)(blob + WIMG_SCAL);
    if (tid < 64) {
        sc[tid]       = b1[l * 64 + tid];
        sc[64 + tid]  = W1c[tid * 129 + 128];
        sc[128 + tid] = b2[l * 64 + tid];
        sc[192 + tid] = W3[l * 64 + tid];
    }
    if (tid == 0) sc[256] = b3[l];
}

/* ================= main HMMA kernel: 2 CTAs/SM, weights via LDG ================= */
__global__ __launch_bounds__(128, 2)
void mlp_hmma_kernel(const float* __restrict__ x, float* __restrict__ out_res)
{
    extern __shared__ unsigned char smem[];
    const int tid = threadIdx.x;
    const int w = tid >> 5, lane = tid & 31;
    const int g = lane >> 2, tg = lane & 3;
    const int tile = blockIdx.x, bb = tile >> 3, t0 = (tile & 7) * 128;
    const int l0 = blockIdx.y * 8;
    const uint32_t sbase = (uint32_t)__cvta_generic_to_shared(smem);

    /* x_t staging */
    {
        const float4* src = (const float4*)(x + (size_t)(bb * TTN + t0 + tid + 2) * 64 + l0);
        float4 v0 = src[0], v1 = src[1];
        float4* d = (float4*)(smem + SM_XT + tid * 32);
        d[0] = v0; d[1] = v1;
    }
    /* A fragments -> smem (once per tile) */
    {
        const uint4* ah = g_a1h + (size_t)tile * 2048;
        const uint4* al = g_a1l + (size_t)tile * 2048;
        for (int i = tid; i < 2048; i += 128) {
            cpa16(sbase + SM_A1H + i * 16, ah + i);
            cpa16(sbase + SM_A1L + i * 16, al + i);
        }
        CPA_COMMIT();
        CPA_WAIT(0);
    }
    __syncthreads();

    const uint4* a1hq = (const uint4*)(smem + SM_A1H);
    const uint4* a1lq = (const uint4*)(smem + SM_A1L);

    #pragma unroll 1
    for (int cj = 0; cj < 8; cj++) {
        const int l = l0 + cj;
        const unsigned char* wbp = g_wimg + (size_t)l * WIMG_STRIDE;   /* global (L1/L2) */
        const float* sc = (const float*)(wbp + WIMG_SCAL);

        /* ---- GEMM1: z1 = X * W1^T (3 split passes) ---- */
        float z1[2][8][4];
        #pragma unroll
        for (int mt = 0; mt < 2; mt++)
            #pragma unroll
            for (int nt = 0; nt < 8; nt++)
                #pragma unroll
                for (int e = 0; e < 4; e++) z1[mt][nt][e] = 0.f;

        #pragma unroll 1
        for (int pass = 0; pass < 3; pass++) {
            const uint4* Aq = (pass < 2) ? a1hq : a1lq;
            const uint2* Bq = (const uint2*)(wbp + ((pass == 1) ? WIMG_W1L : WIMG_W1H));
            #pragma unroll
            for (int kt = 0; kt < 8; kt++) {
                uint4 af0 = Aq[((w * 2 + 0) * 8 + kt) * 32 + lane];
                uint4 af1 = Aq[((w * 2 + 1) * 8 + kt) * 32 + lane];
                uint2 bfr[8];
                #pragma unroll
                for (int nt = 0; nt < 8; nt++)
                    bfr[nt] = __ldg(&Bq[(kt * 8 + nt) * 32 + lane]);
                #pragma unroll
                for (int nt = 0; nt < 8; nt++) {
                    mma_bf16(z1[0][nt][0], z1[0][nt][1], z1[0][nt][2], z1[0][nt][3],
                             af0.x, af0.y, af0.z, af0.w, bfr[nt].x, bfr[nt].y);
                    mma_bf16(z1[1][nt][0], z1[1][nt][1], z1[1][nt][2], z1[1][nt][3],
                             af1.x, af1.y, af1.z, af1.w, bfr[nt].x, bfr[nt].y);
                }
            }
        }

        /* ---- epilogue 1 ---- */
        uint32_t ah[2][4][4], al[2][4][4], cf[2][4][4];
        {
            const float* b1s  = sc;
            const float* w1ls = sc + 64;
            float xtr[2][2];
            #pragma unroll
            for (int mt = 0; mt < 2; mt++) {
                int r0 = (w * 2 + mt) * 16 + g;
                xtr[mt][0] = *(const float*)(smem + SM_XT + r0 * 32 + cj * 4);
                xtr[mt][1] = *(const float*)(smem + SM_XT + (r0 + 8) * 32 + cj * 4);
            }
            #pragma unroll
            for (int mt = 0; mt < 2; mt++)
            #pragma unroll
            for (int kt2 = 0; kt2 < 4; kt2++)
            #pragma unroll
            for (int half = 0; half < 2; half++) {
                int nt = kt2 * 2 + half;
                int col0 = nt * 8 + tg * 2;
                float b1a = __ldg(&b1s[col0]), b1b = __ldg(&b1s[col0 + 1]);
                float wla = __ldg(&w1ls[col0]), wlb = __ldg(&w1ls[col0 + 1]);
                float za = z1[mt][nt][0] + b1a + xtr[mt][0] * wla;
                float zb = z1[mt][nt][1] + b1b + xtr[mt][0] * wlb;
                float zc = z1[mt][nt][2] + b1a + xtr[mt][1] * wla;
                float zd = z1[mt][nt][3] + b1b + xtr[mt][1] * wlb;
                float aa = (za > 0.f) ? za : 0.01f * za;
                float ab = (zb > 0.f) ? zb : 0.01f * zb;
                float ac = (zc > 0.f) ? zc : 0.01f * zc;
                float ad = (zd > 0.f) ? zd : 0.01f * zd;
                ah[mt][kt2][half * 2 + 0] = pkbf(aa, ab);
                ah[mt][kt2][half * 2 + 1] = pkbf(ac, ad);
                al[mt][kt2][half * 2 + 0] = pkbf(aa - bfh(aa), ab - bfh(ab));
                al[mt][kt2][half * 2 + 1] = pkbf(ac - bfh(ac), ad - bfh(ad));
                uint32_t ca = (za > 0.f) ? 0x42C8u : 0x3F80u;
                uint32_t cb = (zb > 0.f) ? 0x42C8u : 0x3F80u;
                uint32_t cc = (zc > 0.f) ? 0x42C8u : 0x3F80u;
                uint32_t cd = (zd > 0.f) ? 0x42C8u : 0x3F80u;
                cf[mt][kt2][half * 2 + 0] = (cb << 16) | ca;
                cf[mt][kt2][half * 2 + 1] = (cd << 16) | cc;
            }
        }

        /* ---- GEMM-t (2 passes) ---- */
        float tA[2][8][4];
        #pragma unroll
        for (int mt = 0; mt < 2; mt++)
            #pragma unroll
            for (int nt = 0; nt < 8; nt++)
                #pragma unroll
                for (int e = 0; e < 4; e++) tA[mt][nt][e] = 0.f;
        #pragma unroll 1
        for (int pass = 0; pass < 2; pass++) {
            const uint2* Bq = (const uint2*)(wbp + (pass ? WIMG_WWL : WIMG_WWH));
            #pragma unroll
            for (int kt = 0; kt < 4; kt++) {
                uint2 bfr[8];
                #pragma unroll
                for (int nt = 0; nt < 8; nt++)
                    bfr[nt] = __ldg(&Bq[(kt * 8 + nt) * 32 + lane]);
                #pragma unroll
                for (int nt = 0; nt < 8; nt++) {
                    mma_bf16(tA[0][nt][0], tA[0][nt][1], tA[0][nt][2], tA[0][nt][3],
                             cf[0][kt][0], cf[0][kt][1], cf[0][kt][2], cf[0][kt][3],
                             bfr[nt].x, bfr[nt].y);
                    mma_bf16(tA[1][nt][0], tA[1][nt][1], tA[1][nt][2], tA[1][nt][3],
                             cf[1][kt][0], cf[1][kt][1], cf[1][kt][2], cf[1][kt][3],
                             bfr[nt].x, bfr[nt].y);
                }
            }
        }

        /* ---- GEMM2 (3 passes) ---- */
        float zA[2][8][4];
        #pragma unroll
        for (int mt = 0; mt < 2; mt++)
            #pragma unroll
            for (int nt = 0; nt < 8; nt++)
                #pragma unroll
                for (int e = 0; e < 4; e++) zA[mt][nt][e] = 0.f;
        #pragma unroll 1
        for (int pass = 0; pass < 3; pass++) {
            const uint32_t (*Af)[4][4] = (pass < 2) ? ah : al;
            const uint2* Bq = (const uint2*)(wbp + ((pass == 1) ? WIMG_W2L : WIMG_W2H));
            #pragma unroll
            for (int kt = 0; kt < 4; kt++) {
                uint2 bfr[8];
                #pragma unroll
                for (int nt = 0; nt < 8; nt++)
                    bfr[nt] = __ldg(&Bq[(kt * 8 + nt) * 32 + lane]);
                #pragma unroll
                for (int nt = 0; nt < 8; nt++) {
                    mma_bf16(zA[0][nt][0], zA[0][nt][1], zA[0][nt][2], zA[0][nt][3],
                             Af[0][kt][0], Af[0][kt][1], Af[0][kt][2], Af[0][kt][3],
                             bfr[nt].x, bfr[nt].y);
                    mma_bf16(zA[1][nt][0], zA[1][nt][1], zA[1][nt][2], zA[1][nt][3],
                             Af[1][kt][0], Af[1][kt][1], Af[1][kt][2], Af[1][kt][3],
                             bfr[nt].x, bfr[nt].y);
                }
            }
        }

        /* ---- epilogue 2 ---- */
        {
            const float* b2s = sc + 128;
            const float* w3s = sc + 192;
            const float b3v = __ldg(&sc[256]);
            float po[2][2] = {{0.f, 0.f}, {0.f, 0.f}};
            float pd[2][2] = {{0.f, 0.f}, {0.f, 0.f}};
            #pragma unroll
            for (int mt = 0; mt < 2; mt++)
            #pragma unroll
            for (int nt = 0; nt < 8; nt++) {
                int col0 = nt * 8 + tg * 2;
                float b2a = __ldg(&b2s[col0]), b2b = __ldg(&b2s[col0 + 1]);
                float w3a = __ldg(&w3s[col0]), w3b = __ldg(&w3s[col0 + 1]);
                #pragma unroll
                for (int e = 0; e < 4; e++) {
                    int ri = e >> 1;
                    float b2v = (e & 1) ? b2b : b2a;
                    float w3v = (e & 1) ? w3b : w3a;
                    float z2 = zA[mt][nt][e] + b2v;
                    float a2 = (z2 > 0.f) ? z2 : 0.01f * z2;
                    float t2 = ((z2 > 0.f) ? 1.0f : 0.01f) * tA[mt][nt][e];
                    po[mt][ri] = fmaf(a2, w3v, po[mt][ri]);
                    pd[mt][ri] = fmaf(t2, w3v, pd[mt][ri]);
                }
            }
            #pragma unroll
            for (int mt = 0; mt < 2; mt++)
            #pragma unroll
            for (int ri = 0; ri < 2; ri++) {
                float o = po[mt][ri], dd = pd[mt][ri];
                o += __shfl_xor_sync(0xffffffffu, o, 1);
                o += __shfl_xor_sync(0xffffffffu, o, 2);
                dd += __shfl_xor_sync(0xffffffffu, dd, 1);
                dd += __shfl_xor_sync(0xffffffffu, dd, 2);
                if (tg == 0) {
                    int row = (w * 2 + mt) * 16 + g + ri * 8;
                    size_t n = (size_t)bb * LENN + t0 + row;
                    out_res[n * 64 + l]   = o + b3v;
                    g_logpart[n * 64 + l] = logf(fabsf(dd));
                }
            }
        }
    }
}

/* deterministic per-sample sum over 64 channels */
__global__ void reduce_log_kernel(float* __restrict__ out_log)
{
    int n = blockIdx.x * blockDim.x + threadIdx.x;
    const float4* p = reinterpret_cast<const float4*>(g_logpart + (size_t)n * 64);
    float s = 0.f;
    #pragma unroll
    for (int i = 0; i < 16; i++) {
        float4 v = p[i];
        s += (v.x + v.y) + (v.z + v.w);
    }
    out_log[n] = s;
}

extern "C" void kernel_launch(void* const* d_in, const int* in_sizes, int n_in,
                              void* d_out, int out_size)
{
    const float* x  = (const float*)d_in[0];
    const float* W1 = (const float*)d_in[1];
    const float* b1 = (const float*)d_in[2];
    const float* W2 = (const float*)d_in[3];
    const float* b2 = (const float*)d_in[4];
    const float* W3 = (const float*)d_in[5];
    const float* b3 = (const float*)d_in[6];
    float* out = (float*)d_out;

    prep_x_kernel<<<dim3(128, 8), 256>>>(x);
    prep_w_kernel<<<64, 256>>>(W1, b1, W2, b2, W3, b3);

    cudaFuncSetAttribute(mlp_hmma_kernel,
                         cudaFuncAttributeMaxDynamicSharedMemorySize, SM_TOTAL);
    mlp_hmma_kernel<<<dim3(128, 8), 128, SM_TOTAL>>>(x, out);
    reduce_log_kernel<<<NTOT / 256, 256>>>(out + (size_t)NTOT * 64);
}